// round 10
// baseline (speedup 1.0000x reference)
#include <cuda_runtime.h>
#include <cuda_bf16.h>
#include <cstdint>

#define B_   8
#define C_   256
#define N_   4096
#define M_   1024
#define HD_  64
#define EPSV 1e-5f

// ===================== helpers =====================
__device__ __forceinline__ uint32_t smem_u32(const void* p) {
    uint32_t a;
    asm("{ .reg .u64 tmp; cvta.to.shared.u64 tmp, %1; cvt.u32.u64 %0, tmp; }" : "=r"(a) : "l"(p));
    return a;
}
__device__ __forceinline__ void ldmx4(uint32_t r[4], uint32_t addr) {
    asm volatile("ldmatrix.sync.aligned.m8n8.x4.shared.b16 {%0,%1,%2,%3}, [%4];"
                 : "=r"(r[0]), "=r"(r[1]), "=r"(r[2]), "=r"(r[3]) : "r"(addr));
}
__device__ __forceinline__ void mma16816(float c[4], const uint32_t a[4], uint32_t b0, uint32_t b1) {
    asm volatile("mma.sync.aligned.m16n8k16.row.col.f32.bf16.bf16.f32 "
                 "{%0,%1,%2,%3}, {%4,%5,%6,%7}, {%8,%9}, {%0,%1,%2,%3};"
                 : "+f"(c[0]), "+f"(c[1]), "+f"(c[2]), "+f"(c[3])
                 : "r"(a[0]), "r"(a[1]), "r"(a[2]), "r"(a[3]), "r"(b0), "r"(b1));
}
__device__ __forceinline__ float ex2f(float x) {
    float r; asm("ex2.approx.ftz.f32 %0, %1;" : "=f"(r) : "f"(x)); return r;
}
__device__ __forceinline__ uint32_t pack_bf16x2(float lo, float hi) {
    uint32_t r;
    asm("cvt.rn.satfinite.bf16x2.f32 %0, %1, %2;" : "=r"(r) : "f"(hi), "f"(lo));
    return r;
}
__device__ __forceinline__ void cp16(uint32_t dst, const void* src) {
    asm volatile("cp.async.cg.shared.global [%0], [%1], 16;" :: "r"(dst), "l"(src));
}
#define CP_COMMIT() asm volatile("cp.async.commit_group;" ::: "memory")
#define CP_WAIT(n)  asm volatile("cp.async.wait_group %0;" :: "n"(n) : "memory")

// ===================== device scratch =====================
__device__ float g_part[B_ * 256 * 2];
__device__ float g_s[B_ * C_];
__device__ float g_t[B_ * C_];
__device__ __nv_bfloat16 g_xt [(size_t)B_ * N_ * C_];   // RAW x, bf16, [b][n][c]
__device__ __nv_bfloat16 g_xds[(size_t)B_ * M_ * C_];   // RAW pooled x, [b][m][c]
__device__ __nv_bfloat16 g_wqb[C_ * C_];                // base weights (wq has QS folded)
__device__ __nv_bfloat16 g_wkb[HD_ * C_];
__device__ __nv_bfloat16 g_wvb[HD_ * C_];
__device__ __nv_bfloat16 g_wob[C_ * C_];
__device__ __nv_bfloat16 g_wqs[B_ * C_ * C_];           // per-batch norm-folded weights
__device__ __nv_bfloat16 g_wks[B_ * HD_ * C_];
__device__ __nv_bfloat16 g_wvs[B_ * HD_ * C_];
__device__ float g_bq[B_ * C_];                         // per-batch projection biases
__device__ float g_bk[B_ * HD_];
__device__ float g_bv[B_ * HD_];
__device__ __nv_bfloat16 g_qt [(size_t)B_ * N_ * C_];   // Q, [b][n][c]
__device__ __nv_bfloat16 g_kt [B_ * M_ * HD_];          // K, [b][m][d]
__device__ __nv_bfloat16 g_vt [B_ * HD_ * M_];          // V, [b][d][m]
__device__ __nv_bfloat16 g_ao [(size_t)B_ * N_ * C_];   // attn out, [b][n][c]

// ============ fused: stats partials + raw bf16 transpose of x ============
__global__ void reduce1t(const float* __restrict__ x) {
    __shared__ float sm[64 * 65];
    __shared__ float ss[256], sq2[256];
    int b = blockIdx.z, c0 = blockIdx.y * 64, n0 = blockIdx.x * 64;
    int t = threadIdx.x;
    float s = 0.f, sq = 0.f;
#pragma unroll
    for (int i = 0; i < 4; i++) {
        int idx = t + 256 * i;
        int c = idx >> 4, ng = (idx & 15) * 4;
        float4 v = *(const float4*)&x[(size_t)(b * C_ + c0 + c) * N_ + n0 + ng];
        sm[(ng + 0) * 65 + c] = v.x;
        sm[(ng + 1) * 65 + c] = v.y;
        sm[(ng + 2) * 65 + c] = v.z;
        sm[(ng + 3) * 65 + c] = v.w;
        s  += v.x + v.y + v.z + v.w;
        sq += v.x * v.x + v.y * v.y + v.z * v.z + v.w * v.w;
    }
    ss[t] = s; sq2[t] = sq;
    __syncthreads();
#pragma unroll
    for (int i = 0; i < 4; i++) {
        int idx = t + 256 * i;
        int cg = idx & 15, n = idx >> 4;
        const float* r = &sm[n * 65 + cg * 4];
        uint2 o;
        o.x = pack_bf16x2(r[0], r[1]);
        o.y = pack_bf16x2(r[2], r[3]);
        *(uint2*)(g_xt + ((size_t)(b * N_ + n0 + n)) * C_ + c0 + cg * 4) = o;
    }
    for (int o = 128; o > 0; o >>= 1) {
        if (t < o) { ss[t] += ss[t + o]; sq2[t] += sq2[t + o]; }
        __syncthreads();
    }
    if (t == 0) {
        int tile = blockIdx.y * 64 + blockIdx.x;
        g_part[(b * 256 + tile) * 2 + 0] = ss[0];
        g_part[(b * 256 + tile) * 2 + 1] = sq2[0];
    }
}
__global__ void reduce2(const float* __restrict__ gn_w, const float* __restrict__ gn_b) {
    int b = blockIdx.x, t = threadIdx.x;
    __shared__ float ss[256], sq2[256];
    ss[t]  = g_part[(b * 256 + t) * 2 + 0];
    sq2[t] = g_part[(b * 256 + t) * 2 + 1];
    __syncthreads();
    for (int o = 128; o > 0; o >>= 1) {
        if (t < o) { ss[t] += ss[t + o]; sq2[t] += sq2[t + o]; }
        __syncthreads();
    }
    __shared__ float sh_mu, sh_inv;
    if (t == 0) {
        const float invN = 1.0f / (float)(C_ * N_);
        float mu  = ss[0] * invN;
        float var = sq2[0] * invN - mu * mu;
        sh_mu = mu; sh_inv = rsqrtf(var + EPSV);
    }
    __syncthreads();
    float sc = sh_inv * gn_w[t];
    g_s[b * C_ + t] = sc;
    g_t[b * C_ + t] = gn_b[t] - sh_mu * sc;
}

// ============ weight conversion (QS folded into wq) ============
__global__ void cvt_all(const float* __restrict__ wq, const float* __restrict__ wk,
                        const float* __restrict__ wv, const float* __restrict__ wo) {
    const float QS = 0.125f * 1.4426950408889634f;
    int i = blockIdx.x * 256 + threadIdx.x;
    if (i < 65536)       g_wqb[i]          = __float2bfloat16(wq[i] * QS);
    else if (i < 81920)  g_wkb[i - 65536]  = __float2bfloat16(wk[i - 65536]);
    else if (i < 98304)  g_wvb[i - 81920]  = __float2bfloat16(wv[i - 81920]);
    else if (i < 163840) g_wob[i - 98304]  = __float2bfloat16(wo[i - 98304]);
}
// ============ fold GroupNorm into per-batch weights + biases ============
__global__ void scale_bias() {
    int b = blockIdx.x, part = blockIdx.y, t = threadIdx.x;
    __shared__ float s_sh[256], t_sh[256];
    s_sh[t] = g_s[b * C_ + t];
    t_sh[t] = g_t[b * C_ + t];
    __syncthreads();
    if (part == 0) {
        for (int i = t; i < 32768; i += 256) {
            int c = i & 255;
            g_wqs[b * 65536 + i] = __float2bfloat16(__bfloat162float(g_wqb[i]) * s_sh[c]);
        }
    } else if (part == 1) {
        for (int i = t; i < 32768; i += 256) {
            int ii = i + 32768, c = ii & 255;
            g_wqs[b * 65536 + ii] = __float2bfloat16(__bfloat162float(g_wqb[ii]) * s_sh[c]);
        }
    } else if (part == 2) {
        for (int i = t; i < 16384; i += 256) {
            int c = i & 255;
            g_wks[b * 16384 + i] = __float2bfloat16(__bfloat162float(g_wkb[i]) * s_sh[c]);
            g_wvs[b * 16384 + i] = __float2bfloat16(__bfloat162float(g_wvb[i]) * s_sh[c]);
        }
    } else {
        float acc = 0.f;
        for (int c = 0; c < 256; c++) acc += __bfloat162float(g_wqb[t * 256 + c]) * t_sh[c];
        g_bq[b * C_ + t] = acc;
        if (t < 64) {
            float a2 = 0.f;
            for (int c = 0; c < 256; c++) a2 += __bfloat162float(g_wkb[t * 256 + c]) * t_sh[c];
            g_bk[b * HD_ + t] = a2;
        } else if (t < 128) {
            int o = t - 64;
            float a2 = 0.f;
            for (int c = 0; c < 256; c++) a2 += __bfloat162float(g_wvb[o * 256 + c]) * t_sh[c];
            g_bv[b * HD_ + o] = a2;
        }
    }
}
// ============ 2x2 avgpool on raw bf16 xt ============
__global__ void pool_xt() {
    int t = threadIdx.x;
    int idx = blockIdx.x * 4 + (t >> 6);
    int b = idx >> 10, m = idx & 1023;
    int c4 = (t & 63) * 4;
    int nb = (m >> 5) * 128 + (m & 31) * 2;
    const __nv_bfloat16* base = g_xt + ((size_t)b * N_) * C_ + c4;
    float acc[4] = {0.f, 0.f, 0.f, 0.f};
    int offs[4] = {0, 1, 64, 65};
#pragma unroll
    for (int r = 0; r < 4; r++) {
        uint2 v = *(const uint2*)(base + (size_t)(nb + offs[r]) * C_);
        __nv_bfloat162 p0 = *(__nv_bfloat162*)&v.x;
        __nv_bfloat162 p1 = *(__nv_bfloat162*)&v.y;
        acc[0] += __bfloat162float(p0.x); acc[1] += __bfloat162float(p0.y);
        acc[2] += __bfloat162float(p1.x); acc[3] += __bfloat162float(p1.y);
    }
    uint2 o;
    o.x = pack_bf16x2(acc[0] * 0.25f, acc[1] * 0.25f);
    o.y = pack_bf16x2(acc[2] * 0.25f, acc[3] * 0.25f);
    *(uint2*)(g_xds + ((size_t)b * M_ + m) * C_ + c4) = o;
}

// ===================== projection GEMM, cp.async double-buffered ==============
// CTA: 128 rows x NT cols, K=256 in 8 chunks of 32. Per-batch weights via wstride.
// mode 0: bf16 out[row][N] (+bias); mode 1: bf16 V transposed [d][M] (+bias);
// mode 2: fp32 channel-major residual out (no bias)
template<int NT>
__global__ void __launch_bounds__(256) proj_mma(
    const __nv_bfloat16* __restrict__ A, const __nv_bfloat16* __restrict__ Bw,
    int rows, int N, long long wstride, int mode, const float* __restrict__ bias,
    __nv_bfloat16* __restrict__ outb, float* __restrict__ outf,
    const float* __restrict__ xres, const float* __restrict__ gamma)
{
    extern __shared__ char dsm[];
    __nv_bfloat16* As = (__nv_bfloat16*)dsm;               // [2][128][40]
    __nv_bfloat16* Bs = (__nv_bfloat16*)(dsm + 20480);     // [2][NT][40]
    float* Cs = (float*)dsm;                                // [NT][132] epilogue (mode2)

    constexpr int NFR = NT / 16;
    int t = threadIdx.x, lane = t & 31, wid = t >> 5;
    int wm = wid & 3, wn = wid >> 2;
    int b = blockIdx.z, row0 = blockIdx.x * 128, n0 = blockIdx.y * NT;
    int g = lane >> 2, qt = lane & 3;

    float acc[2][NFR][4];
#pragma unroll
    for (int mi = 0; mi < 2; mi++)
#pragma unroll
        for (int ni = 0; ni < NFR; ni++)
#pragma unroll
            for (int e = 0; e < 4; e++) acc[mi][ni][e] = 0.f;

    const __nv_bfloat16* Ag = A + ((size_t)b * rows + row0) * 256;
    const __nv_bfloat16* Bg = Bw + (size_t)b * wstride;

    auto issue = [&](int k0, int buf) {
        __nv_bfloat16* Asb = As + buf * (128 * 40);
        __nv_bfloat16* Bsb = Bs + buf * (NT * 40);
#pragma unroll
        for (int i = 0; i < 2; i++) {
            int idx = t + 256 * i;
            int r = idx >> 2, kc = (idx & 3) * 8;
            cp16(smem_u32(Asb + r * 40 + kc), Ag + (size_t)r * 256 + k0 + kc);
        }
#pragma unroll
        for (int i = 0; i < NT / 64; i++) {
            int idx = t + 256 * i;
            int r = idx >> 2, kc = (idx & 3) * 8;
            cp16(smem_u32(Bsb + r * 40 + kc), Bg + (size_t)(n0 + r) * 256 + k0 + kc);
        }
        CP_COMMIT();
    };

    issue(0, 0);
    for (int c = 0; c < 8; c++) {
        if (c < 7) { issue((c + 1) * 32, (c + 1) & 1); CP_WAIT(1); }
        else       { CP_WAIT(0); }
        __syncthreads();
        __nv_bfloat16* Asb = As + (c & 1) * (128 * 40);
        __nv_bfloat16* Bsb = Bs + (c & 1) * (NT * 40);
#pragma unroll
        for (int k16 = 0; k16 < 32; k16 += 16) {
            uint32_t af[2][4];
#pragma unroll
            for (int mi = 0; mi < 2; mi++) {
                uint32_t addr = smem_u32(Asb + (wm * 32 + mi * 16 + (lane & 15)) * 40
                                         + k16 + (lane >> 4) * 8);
                ldmx4(af[mi], addr);
            }
#pragma unroll
            for (int np = 0; np < NFR / 2; np++) {
                uint32_t bfm[4];
                uint32_t addr = smem_u32(Bsb + (wn * (NT / 2) + np * 16 + (lane & 7) + ((lane >> 4) & 1) * 8) * 40
                                         + k16 + ((lane >> 3) & 1) * 8);
                ldmx4(bfm, addr);
                mma16816(acc[0][np * 2 + 0], af[0], bfm[0], bfm[1]);
                mma16816(acc[0][np * 2 + 1], af[0], bfm[2], bfm[3]);
                mma16816(acc[1][np * 2 + 0], af[1], bfm[0], bfm[1]);
                mma16816(acc[1][np * 2 + 1], af[1], bfm[2], bfm[3]);
            }
        }
        __syncthreads();
    }

    if (mode == 0) {
        const float* bp = bias + (size_t)b * N + n0 + wn * (NT / 2);
#pragma unroll
        for (int mi = 0; mi < 2; mi++)
#pragma unroll
            for (int ni = 0; ni < NFR; ni++) {
                int r = row0 + wm * 32 + mi * 16 + g;
                int cl = ni * 8 + 2 * qt;
                int col = n0 + wn * (NT / 2) + cl;
                float b0 = bp[cl], b1 = bp[cl + 1];
                *(uint32_t*)(outb + ((size_t)b * rows + r) * N + col) =
                    pack_bf16x2(acc[mi][ni][0] + b0, acc[mi][ni][1] + b1);
                *(uint32_t*)(outb + ((size_t)b * rows + r + 8) * N + col) =
                    pack_bf16x2(acc[mi][ni][2] + b0, acc[mi][ni][3] + b1);
            }
    } else if (mode == 1) {
        const float* bp = bias + (size_t)b * N + n0 + wn * (NT / 2);
#pragma unroll
        for (int mi = 0; mi < 2; mi++)
#pragma unroll
            for (int ni = 0; ni < NFR; ni++) {
                int r = row0 + wm * 32 + mi * 16 + g;
                int cl = ni * 8 + 2 * qt;
                int col = n0 + wn * (NT / 2) + cl;
                float b0 = bp[cl], b1 = bp[cl + 1];
                outb[((size_t)b * HD_ + col)     * M_ + r]     = __float2bfloat16(acc[mi][ni][0] + b0);
                outb[((size_t)b * HD_ + col + 1) * M_ + r]     = __float2bfloat16(acc[mi][ni][1] + b1);
                outb[((size_t)b * HD_ + col)     * M_ + r + 8] = __float2bfloat16(acc[mi][ni][2] + b0);
                outb[((size_t)b * HD_ + col + 1) * M_ + r + 8] = __float2bfloat16(acc[mi][ni][3] + b1);
            }
    } else {
#pragma unroll
        for (int mi = 0; mi < 2; mi++)
#pragma unroll
            for (int ni = 0; ni < NFR; ni++) {
                int rL = wm * 32 + mi * 16 + g;
                int cL = wn * (NT / 2) + ni * 8 + 2 * qt;
                Cs[cL * 132 + rL]           = acc[mi][ni][0];
                Cs[(cL + 1) * 132 + rL]     = acc[mi][ni][1];
                Cs[cL * 132 + rL + 8]       = acc[mi][ni][2];
                Cs[(cL + 1) * 132 + rL + 8] = acc[mi][ni][3];
            }
        __syncthreads();
#pragma unroll
        for (int i = 0; i < NT / 8; i++) {
            int idx = t + 256 * i;
            int col = idx >> 5, r4 = (idx & 31) * 4;
            float4 v = *(float4*)&Cs[col * 132 + r4];
            size_t off = ((size_t)b * C_ + n0 + col) * (size_t)N_ + row0 + r4;
            float gch = gamma[n0 + col];
            float4 xr = *(const float4*)&xres[off];
            v.x = fmaf(gch, v.x, xr.x);
            v.y = fmaf(gch, v.y, xr.y);
            v.z = fmaf(gch, v.z, xr.z);
            v.w = fmaf(gch, v.w, xr.w);
            *(float4*)&outf[off] = v;
        }
    }
}

// ============ attention: 128 q/CTA, 8 warps, bf16 HMMA, cp.async double-buffer ========
__global__ void __launch_bounds__(256) attn_mma() {
    __shared__ __align__(16) __nv_bfloat16 Ks[2][64 * 72];
    __shared__ __align__(16) __nv_bfloat16 Vs[2][64 * 72];

    int t = threadIdx.x, lane = t & 31, w = t >> 5;
    int g = lane >> 2, qt = lane & 3;
    int bh = blockIdx.y, b = bh >> 2, h = bh & 3;
    int n0 = blockIdx.x * 128;

    const __nv_bfloat16* Kg = g_kt + (size_t)b * M_ * HD_;
    const __nv_bfloat16* Vg = g_vt + (size_t)b * HD_ * M_;

    auto issue = [&](int m0, int buf) {
#pragma unroll
        for (int i = 0; i < 2; i++) {
            int idx = t + 256 * i;
            int r = idx >> 3, cc = (idx & 7) * 8;
            cp16(smem_u32(&Ks[buf][r * 72 + cc]), Kg + (size_t)(m0 + r) * HD_ + cc);
            cp16(smem_u32(&Vs[buf][r * 72 + cc]), Vg + (size_t)r * M_ + m0 + cc);
        }
        CP_COMMIT();
    };
    issue(0, 0);

    uint32_t qf[4][4];
    const __nv_bfloat16* Qg = g_qt + ((size_t)b * N_ + n0 + w * 16) * C_ + h * HD_;
#pragma unroll
    for (int k16 = 0; k16 < 4; k16++) {
        qf[k16][0] = *(const uint32_t*)(Qg + (size_t)g * C_       + k16 * 16 + 2 * qt);
        qf[k16][1] = *(const uint32_t*)(Qg + (size_t)(g + 8) * C_ + k16 * 16 + 2 * qt);
        qf[k16][2] = *(const uint32_t*)(Qg + (size_t)g * C_       + k16 * 16 + 8 + 2 * qt);
        qf[k16][3] = *(const uint32_t*)(Qg + (size_t)(g + 8) * C_ + k16 * 16 + 8 + 2 * qt);
    }

    float oacc[8][4];
#pragma unroll
    for (int ni = 0; ni < 8; ni++)
#pragma unroll
        for (int e = 0; e < 4; e++) oacc[ni][e] = 0.f;
    float lsum0 = 0.f, lsum1 = 0.f;

    for (int tile = 0; tile < 16; tile++) {
        if (tile < 15) { issue((tile + 1) * 64, (tile + 1) & 1); CP_WAIT(1); }
        else           { CP_WAIT(0); }
        __syncthreads();
        const __nv_bfloat16* Kb = Ks[tile & 1];
        const __nv_bfloat16* Vb = Vs[tile & 1];

        float sacc[8][4];
#pragma unroll
        for (int ni = 0; ni < 8; ni++)
#pragma unroll
            for (int e = 0; e < 4; e++) sacc[ni][e] = 0.f;
#pragma unroll
        for (int k16 = 0; k16 < 4; k16++) {
#pragma unroll
            for (int np = 0; np < 4; np++) {
                uint32_t bfm[4];
                uint32_t addr = smem_u32(Kb + (np * 16 + (lane & 7) + ((lane >> 4) & 1) * 8) * 72
                                         + k16 * 16 + ((lane >> 3) & 1) * 8);
                ldmx4(bfm, addr);
                mma16816(sacc[np * 2 + 0], qf[k16], bfm[0], bfm[1]);
                mma16816(sacc[np * 2 + 1], qf[k16], bfm[2], bfm[3]);
            }
        }

        uint32_t pa[4][4];
#pragma unroll
        for (int j = 0; j < 4; j++) {
            float e00 = ex2f(sacc[2 * j][0]),     e01 = ex2f(sacc[2 * j][1]);
            float e10 = ex2f(sacc[2 * j][2]),     e11 = ex2f(sacc[2 * j][3]);
            float f00 = ex2f(sacc[2 * j + 1][0]), f01 = ex2f(sacc[2 * j + 1][1]);
            float f10 = ex2f(sacc[2 * j + 1][2]), f11 = ex2f(sacc[2 * j + 1][3]);
            lsum0 += e00 + e01 + f00 + f01;
            lsum1 += e10 + e11 + f10 + f11;
            pa[j][0] = pack_bf16x2(e00, e01);
            pa[j][1] = pack_bf16x2(e10, e11);
            pa[j][2] = pack_bf16x2(f00, f01);
            pa[j][3] = pack_bf16x2(f10, f11);
        }

#pragma unroll
        for (int k16 = 0; k16 < 4; k16++) {
#pragma unroll
            for (int np = 0; np < 4; np++) {
                uint32_t bfm[4];
                uint32_t addr = smem_u32(Vb + (np * 16 + (lane & 7) + ((lane >> 4) & 1) * 8) * 72
                                         + k16 * 16 + ((lane >> 3) & 1) * 8);
                ldmx4(bfm, addr);
                mma16816(oacc[np * 2 + 0], pa[k16], bfm[0], bfm[1]);
                mma16816(oacc[np * 2 + 1], pa[k16], bfm[2], bfm[3]);
            }
        }
        __syncthreads();
    }

#pragma unroll
    for (int o = 1; o <= 2; o <<= 1) {
        lsum0 += __shfl_xor_sync(0xffffffffu, lsum0, o);
        lsum1 += __shfl_xor_sync(0xffffffffu, lsum1, o);
    }
    float inv0 = 1.0f / lsum0, inv1 = 1.0f / lsum1;

    __nv_bfloat16* Og = g_ao + ((size_t)b * N_ + n0 + w * 16) * C_ + h * HD_;
#pragma unroll
    for (int ni = 0; ni < 8; ni++) {
        int col = ni * 8 + 2 * qt;
        *(uint32_t*)(Og + (size_t)g * C_ + col) =
            pack_bf16x2(oacc[ni][0] * inv0, oacc[ni][1] * inv0);
        *(uint32_t*)(Og + (size_t)(g + 8) * C_ + col) =
            pack_bf16x2(oacc[ni][2] * inv1, oacc[ni][3] * inv1);
    }
}

// ===================== launch =====================
extern "C" void kernel_launch(void* const* d_in, const int* in_sizes, int n_in,
                              void* d_out, int out_size) {
    const float* x    = (const float*)d_in[0];
    const float* gn_w = (const float*)d_in[1];
    const float* gn_b = (const float*)d_in[2];
    const float* wq   = (const float*)d_in[3];
    const float* wk   = (const float*)d_in[4];
    const float* wv   = (const float*)d_in[5];
    const float* wo   = (const float*)d_in[6];
    const float* gamma= (const float*)d_in[7];
    float* out = (float*)d_out;

    __nv_bfloat16 *pxt, *pxds, *pwqs, *pwks, *pwvs, *pwob, *pqt, *pkt, *pvt, *pao;
    float *pbq, *pbk, *pbv;
    cudaGetSymbolAddress((void**)&pxt,  g_xt);
    cudaGetSymbolAddress((void**)&pxds, g_xds);
    cudaGetSymbolAddress((void**)&pwqs, g_wqs);
    cudaGetSymbolAddress((void**)&pwks, g_wks);
    cudaGetSymbolAddress((void**)&pwvs, g_wvs);
    cudaGetSymbolAddress((void**)&pwob, g_wob);
    cudaGetSymbolAddress((void**)&pbq,  g_bq);
    cudaGetSymbolAddress((void**)&pbk,  g_bk);
    cudaGetSymbolAddress((void**)&pbv,  g_bv);
    cudaGetSymbolAddress((void**)&pqt,  g_qt);
    cudaGetSymbolAddress((void**)&pkt,  g_kt);
    cudaGetSymbolAddress((void**)&pvt,  g_vt);
    cudaGetSymbolAddress((void**)&pao,  g_ao);

    cudaFuncSetAttribute(proj_mma<128>, cudaFuncAttributeMaxDynamicSharedMemorySize, 67584);

    cvt_all<<<640, 256>>>(wq, wk, wv, wo);
    reduce1t<<<dim3(64, 4, 8), 256>>>(x);
    reduce2<<<8, 256>>>(gn_w, gn_b);
    scale_bias<<<dim3(8, 4), 256>>>();
    pool_xt<<<2048, 256>>>();

    // Q = xt_raw @ (wq*s_b)^T + bias_q  -> bf16 [b][n][256]
    proj_mma<128><<<dim3(32, 2, 8), 256, 40960>>>(pxt, pwqs, N_, 256, 65536LL, 0, pbq,
                                                  pqt, nullptr, nullptr, nullptr);
    // K = xds_raw @ (wk*s_b)^T + bias_k -> bf16 [b][m][64]
    proj_mma<64><<<dim3(8, 1, 8), 256, 30720>>>(pxds, pwks, M_, 64, 16384LL, 0, pbk,
                                                pkt, nullptr, nullptr, nullptr);
    // V -> bf16 transposed [b][d][1024], + bias_v
    proj_mma<64><<<dim3(8, 1, 8), 256, 30720>>>(pxds, pwvs, M_, 64, 16384LL, 1, pbv,
                                                pvt, nullptr, nullptr, nullptr);

    attn_mma<<<dim3(32, 32), 256>>>();

    // out = x + gamma * (ao @ wo^T), channel-major fp32
    proj_mma<128><<<dim3(32, 2, 8), 256, 67584>>>(pao, pwob, N_, 256, 0LL, 2, nullptr,
                                                  nullptr, out, x, gamma);
}